// round 5
// baseline (speedup 1.0000x reference)
#include <cuda_runtime.h>

#define LCOLS 4096
#define NSTAGES 12
#define RROWS 4
#define TPB 512
#define NBATCH 8192

// Swizzle: XOR bit4 with j's bit11, bit2 with j's bit5. Only touches bits >=2;
// bits 5/11 constant within a 4-aligned group -> float4 halves stay contiguous.
__device__ __forceinline__ int swz(int j) {
    return j ^ (((j >> 11) & 1) << 4) ^ (((j >> 5) & 1) << 2);
}

// y[j] <- W[s][j][0]*y[j] + W[s][j][1]*y[j ^ (1<<s)]
// Phase 1: thread owns 8 contiguous cols (bits 0-2 in-thread, bits 3-7 lane -> shfl)
//          -> stages 0..7. One swizzled smem store.
// Phase 2: thread gathers j = b11*2048 + k*256 + low8 (k = bits 8-10 in-thread,
//          b11 = lane bit 4 -> shfl mask 16) -> stages 8..11. Direct global store.
// R=4 + 64-reg budget -> 2 blocks/SM (32 warps) to hide shfl/LDS latency.
__global__ __launch_bounds__(TPB, 2)
void butterfly_kernel(const float* __restrict__ x,
                      const float* __restrict__ W,
                      float* __restrict__ out)
{
    extern __shared__ float sm[];   // RROWS * LCOLS floats = 64 KB
    const int tid  = threadIdx.x;
    const int row0 = blockIdx.x * RROWS;
    const int j0   = tid * 8;

    float y[RROWS][8];

    // ---- load R rows x 8 cols, vectorized & coalesced ----
    #pragma unroll
    for (int r = 0; r < RROWS; ++r) {
        const float4* p = reinterpret_cast<const float4*>(
            x + (size_t)(row0 + r) * LCOLS + j0);
        float4 a = __ldg(p);
        float4 b = __ldg(p + 1);
        y[r][0]=a.x; y[r][1]=a.y; y[r][2]=a.z; y[r][3]=a.w;
        y[r][4]=b.x; y[r][5]=b.y; y[r][6]=b.z; y[r][7]=b.w;
    }

    // ---- phase 1: stages 0..7 (regs + shfl), stage-major to cap live regs ----
    #pragma unroll
    for (int s = 0; s < 8; ++s) {
        float w0[8], w1[8];
        const float4* wp = reinterpret_cast<const float4*>(
            W + (size_t)s * (LCOLS * 2) + j0 * 2);
        float4 wA = __ldg(wp + 0), wB = __ldg(wp + 1);
        float4 wC = __ldg(wp + 2), wD = __ldg(wp + 3);
        w0[0]=wA.x; w1[0]=wA.y; w0[1]=wA.z; w1[1]=wA.w;
        w0[2]=wB.x; w1[2]=wB.y; w0[3]=wB.z; w1[3]=wB.w;
        w0[4]=wC.x; w1[4]=wC.y; w0[5]=wC.z; w1[5]=wC.w;
        w0[6]=wD.x; w1[6]=wD.y; w0[7]=wD.z; w1[7]=wD.w;

        if (s < 3) {
            const int d = 1 << s;                     // 1,2,4 in-thread
            #pragma unroll
            for (int r = 0; r < RROWS; ++r) {
                float nt[8];
                #pragma unroll
                for (int c = 0; c < 8; ++c)
                    nt[c] = fmaf(w0[c], y[r][c], w1[c] * y[r][c ^ d]);
                #pragma unroll
                for (int c = 0; c < 8; ++c) y[r][c] = nt[c];
            }
        } else {
            const int m = 1 << (s - 3);               // lane xor 1..16
            #pragma unroll
            for (int r = 0; r < RROWS; ++r) {
                #pragma unroll
                for (int c = 0; c < 8; ++c) {
                    float p = __shfl_xor_sync(0xffffffffu, y[r][c], m);
                    y[r][c] = fmaf(w0[c], y[r][c], w1[c] * p);
                }
            }
        }
    }

    // ---- single swizzled smem store: element j lands at sm[swz(j)] ----
    {
        const int s0 = swz(j0);        // elements j0..j0+3
        const int s1 = swz(j0 + 4);    // elements j0+4..j0+7
        #pragma unroll
        for (int r = 0; r < RROWS; ++r) {
            *reinterpret_cast<float4*>(&sm[r * LCOLS + s0]) =
                make_float4(y[r][0], y[r][1], y[r][2], y[r][3]);
            *reinterpret_cast<float4*>(&sm[r * LCOLS + s1]) =
                make_float4(y[r][4], y[r][5], y[r][6], y[r][7]);
        }
    }
    __syncthreads();

    // ---- phase 2: stages 8..11, stage-major (one stage's weights live) ----
    const int l     = tid & 31;
    const int w     = tid >> 5;
    const int b11   = l >> 4;                // stage-11 partner = lane ^ 16
    const int low8  = (w << 4) | (l & 15);   // bits 0..7 of j
    const int jbase = b11 * 2048 + low8;     // j(k) = jbase + k*256
    const int sjbase = swz(jbase);           // bits 5,11 of j constant per thread

    float v[RROWS][8];
    #pragma unroll
    for (int r = 0; r < RROWS; ++r)
        #pragma unroll
        for (int k = 0; k < 8; ++k)
            v[r][k] = sm[r * LCOLS + sjbase + k * 256];   // conflict-free gather

    // stages 8,9,10 : butterflies on k bits 0,1,2
    #pragma unroll
    for (int sb = 0; sb < 3; ++sb) {
        float w0[8], w1[8];
        #pragma unroll
        for (int k = 0; k < 8; ++k) {
            const float2 ww = __ldg(reinterpret_cast<const float2*>(
                W + (size_t)(8 + sb) * (LCOLS * 2) + 2 * (jbase + k * 256)));
            w0[k] = ww.x;
            w1[k] = ww.y;
        }
        const int d = 1 << sb;
        #pragma unroll
        for (int r = 0; r < RROWS; ++r) {
            float nv[8];
            #pragma unroll
            for (int k = 0; k < 8; ++k)
                nv[k] = fmaf(w0[k], v[r][k], w1[k] * v[r][k ^ d]);
            #pragma unroll
            for (int k = 0; k < 8; ++k) v[r][k] = nv[k];
        }
    }

    // stage 11 : partner is lane^16 (b11 flip)
    {
        float w0[8], w1[8];
        #pragma unroll
        for (int k = 0; k < 8; ++k) {
            const float2 ww = __ldg(reinterpret_cast<const float2*>(
                W + (size_t)11 * (LCOLS * 2) + 2 * (jbase + k * 256)));
            w0[k] = ww.x;
            w1[k] = ww.y;
        }
        #pragma unroll
        for (int r = 0; r < RROWS; ++r) {
            #pragma unroll
            for (int k = 0; k < 8; ++k) {
                float p = __shfl_xor_sync(0xffffffffu, v[r][k], 16);
                v[r][k] = fmaf(w0[k], v[r][k], w1[k] * p);
            }
        }
    }

    // direct global store: per k, lanes 0-15 / 16-31 each cover 64B runs
    #pragma unroll
    for (int r = 0; r < RROWS; ++r) {
        float* op = out + (size_t)(row0 + r) * LCOLS + jbase;
        #pragma unroll
        for (int k = 0; k < 8; ++k)
            op[k * 256] = v[r][k];
    }
}

extern "C" void kernel_launch(void* const* d_in, const int* in_sizes, int n_in,
                              void* d_out, int out_size) {
    const float* x;
    const float* W;
    if (in_sizes[0] == NSTAGES * LCOLS * 2) {   // W has 98304 elements
        W = (const float*)d_in[0];
        x = (const float*)d_in[1];
    } else {
        x = (const float*)d_in[0];
        W = (const float*)d_in[1];
    }
    float* out = (float*)d_out;

    const int smem_bytes = RROWS * LCOLS * sizeof(float);  // 64 KB
    cudaFuncSetAttribute(butterfly_kernel,
                         cudaFuncAttributeMaxDynamicSharedMemorySize, smem_bytes);
    butterfly_kernel<<<NBATCH / RROWS, TPB, smem_bytes>>>(x, W, out);
}

// round 6
// speedup vs baseline: 1.1754x; 1.1754x over previous
#include <cuda_runtime.h>

#define LCOLS 4096
#define NSTAGES 12
#define RROWS 8
#define TPB 512
#define NBATCH 8192

// Swizzle: XOR bit4 with j's bit11, bit2 with j's bit5. Only touches bits >=2;
// bits 5/11 constant within a 4-aligned group -> float4 halves stay contiguous.
__device__ __forceinline__ int swz(int j) {
    return j ^ (((j >> 11) & 1) << 4) ^ (((j >> 5) & 1) << 2);
}

// y[j] <- W[s][j][0]*y[j] + W[s][j][1]*y[j ^ (1<<s)]
// Phase 1: thread owns 8 contiguous cols (bits 0-2 in-thread, bits 3-7 lane -> shfl)
//          -> stages 0..7. One swizzled smem store. Weights double-buffered.
// Phase 2: thread gathers j = b11*2048 + k*256 + low8 (k = bits 8-10 in-thread,
//          b11 = lane bit 4 -> shfl mask 16) -> stages 8..11. Row-pipelined LDS.
__global__ __launch_bounds__(TPB, 1)
void butterfly_kernel(const float* __restrict__ x,
                      const float* __restrict__ W,
                      float* __restrict__ out)
{
    extern __shared__ float sm[];   // RROWS * LCOLS floats = 128 KB
    const int tid  = threadIdx.x;
    const int row0 = blockIdx.x * RROWS;
    const int j0   = tid * 8;

    float y[RROWS][8];

    // ---- load 8 rows x 8 cols, vectorized & coalesced ----
    #pragma unroll
    for (int r = 0; r < RROWS; ++r) {
        const float4* p = reinterpret_cast<const float4*>(
            x + (size_t)(row0 + r) * LCOLS + j0);
        float4 a = __ldg(p);
        float4 b = __ldg(p + 1);
        y[r][0]=a.x; y[r][1]=a.y; y[r][2]=a.z; y[r][3]=a.w;
        y[r][4]=b.x; y[r][5]=b.y; y[r][6]=b.z; y[r][7]=b.w;
    }

    // ---- phase 1: stages 0..7 with double-buffered weight loads ----
    float4 wA, wB, wC, wD;
    {
        const float4* wp = reinterpret_cast<const float4*>(W + (size_t)0 + j0 * 2);
        wA = __ldg(wp + 0); wB = __ldg(wp + 1);
        wC = __ldg(wp + 2); wD = __ldg(wp + 3);
    }
    #pragma unroll
    for (int s = 0; s < 8; ++s) {
        float4 nA, nB, nC, nD;
        if (s < 7) {   // issue next stage's loads before this stage's compute
            const float4* np = reinterpret_cast<const float4*>(
                W + (size_t)(s + 1) * (LCOLS * 2) + j0 * 2);
            nA = __ldg(np + 0); nB = __ldg(np + 1);
            nC = __ldg(np + 2); nD = __ldg(np + 3);
        }

        float w0[8], w1[8];
        w0[0]=wA.x; w1[0]=wA.y; w0[1]=wA.z; w1[1]=wA.w;
        w0[2]=wB.x; w1[2]=wB.y; w0[3]=wB.z; w1[3]=wB.w;
        w0[4]=wC.x; w1[4]=wC.y; w0[5]=wC.z; w1[5]=wC.w;
        w0[6]=wD.x; w1[6]=wD.y; w0[7]=wD.z; w1[7]=wD.w;

        if (s < 3) {
            const int d = 1 << s;                     // 1,2,4 in-thread
            #pragma unroll
            for (int r = 0; r < RROWS; ++r) {
                float nt[8];
                #pragma unroll
                for (int c = 0; c < 8; ++c)
                    nt[c] = fmaf(w0[c], y[r][c], w1[c] * y[r][c ^ d]);
                #pragma unroll
                for (int c = 0; c < 8; ++c) y[r][c] = nt[c];
            }
        } else {
            const int m = 1 << (s - 3);               // lane xor 1..16
            #pragma unroll
            for (int r = 0; r < RROWS; ++r) {
                #pragma unroll
                for (int c = 0; c < 8; ++c) {
                    float p = __shfl_xor_sync(0xffffffffu, y[r][c], m);
                    y[r][c] = fmaf(w0[c], y[r][c], w1[c] * p);
                }
            }
        }

        if (s < 7) { wA = nA; wB = nB; wC = nC; wD = nD; }
    }

    // ---- single swizzled smem store: element j lands at sm[swz(j)] ----
    {
        const int s0 = swz(j0);        // elements j0..j0+3
        const int s1 = swz(j0 + 4);    // elements j0+4..j0+7
        #pragma unroll
        for (int r = 0; r < RROWS; ++r) {
            *reinterpret_cast<float4*>(&sm[r * LCOLS + s0]) =
                make_float4(y[r][0], y[r][1], y[r][2], y[r][3]);
            *reinterpret_cast<float4*>(&sm[r * LCOLS + s1]) =
                make_float4(y[r][4], y[r][5], y[r][6], y[r][7]);
        }
    }
    __syncthreads();

    // ---- phase 2: stages 8..11 ----
    const int l     = tid & 31;
    const int w     = tid >> 5;
    const int b11   = l >> 4;                // stage-11 partner = lane ^ 16
    const int low8  = (w << 4) | (l & 15);   // bits 0..7 of j
    const int jbase = b11 * 2048 + low8;     // j(k) = jbase + k*256
    const int sjbase = swz(jbase);           // bits 5,11 of j constant per thread

    // weights for stages 8..11 loaded up-front; latency overlaps first gathers
    float w0p[4][8], w1p[4][8];
    #pragma unroll
    for (int s4 = 0; s4 < 4; ++s4) {
        #pragma unroll
        for (int k = 0; k < 8; ++k) {
            const float2 ww = __ldg(reinterpret_cast<const float2*>(
                W + (size_t)(8 + s4) * (LCOLS * 2) + 2 * (jbase + k * 256)));
            w0p[s4][k] = ww.x;
            w1p[s4][k] = ww.y;
        }
    }

    // row-pipelined gather: prefetch row r+1 while computing row r
    float vnext[8];
    #pragma unroll
    for (int k = 0; k < 8; ++k)
        vnext[k] = sm[0 * LCOLS + sjbase + k * 256];

    #pragma unroll
    for (int r = 0; r < RROWS; ++r) {
        float v[8];
        #pragma unroll
        for (int k = 0; k < 8; ++k) v[k] = vnext[k];

        if (r < RROWS - 1) {
            #pragma unroll
            for (int k = 0; k < 8; ++k)
                vnext[k] = sm[(r + 1) * LCOLS + sjbase + k * 256];
        }

        // stages 8,9,10 : butterflies on k bits 0,1,2
        #pragma unroll
        for (int sb = 0; sb < 3; ++sb) {
            const int d = 1 << sb;
            float nv[8];
            #pragma unroll
            for (int k = 0; k < 8; ++k)
                nv[k] = fmaf(w0p[sb][k], v[k], w1p[sb][k] * v[k ^ d]);
            #pragma unroll
            for (int k = 0; k < 8; ++k) v[k] = nv[k];
        }

        // stage 11 : partner is lane^16 (b11 flip)
        #pragma unroll
        for (int k = 0; k < 8; ++k) {
            float p = __shfl_xor_sync(0xffffffffu, v[k], 16);
            v[k] = fmaf(w0p[3][k], v[k], w1p[3][k] * p);
        }

        // direct global store: per k, lanes 0-15 / 16-31 each cover 64B runs
        float* op = out + (size_t)(row0 + r) * LCOLS + jbase;
        #pragma unroll
        for (int k = 0; k < 8; ++k)
            op[k * 256] = v[k];
    }
}

extern "C" void kernel_launch(void* const* d_in, const int* in_sizes, int n_in,
                              void* d_out, int out_size) {
    const float* x;
    const float* W;
    if (in_sizes[0] == NSTAGES * LCOLS * 2) {   // W has 98304 elements
        W = (const float*)d_in[0];
        x = (const float*)d_in[1];
    } else {
        x = (const float*)d_in[0];
        W = (const float*)d_in[1];
    }
    float* out = (float*)d_out;

    const int smem_bytes = RROWS * LCOLS * sizeof(float);  // 128 KB
    cudaFuncSetAttribute(butterfly_kernel,
                         cudaFuncAttributeMaxDynamicSharedMemorySize, smem_bytes);
    butterfly_kernel<<<NBATCH / RROWS, TPB, smem_bytes>>>(x, W, out);
}

// round 7
// speedup vs baseline: 1.3297x; 1.1313x over previous
#include <cuda_runtime.h>

#define LCOLS 4096
#define NSTAGES 12
#define RROWS 8
#define TPB 512
#define NBATCH 8192

// Swizzle: XOR bit4 with j's bit11, bit2 with j's bit5.
__device__ __forceinline__ int swz(int j) {
    return j ^ (((j >> 11) & 1) << 4) ^ (((j >> 5) & 1) << 2);
}

// Swap roles of register bit MC and lane bit ML for one row of 8 regs.
// Element with (regbit=a, lanebit=b): stays if a==b, else exchanged with the
// lane partner. Cost: 4 shfl + selects (vs 8 shfl for a full shfl-butterfly).
template <int MC, int ML>
__device__ __forceinline__ void bitswap(float* yr, bool lo) {
    #pragma unroll
    for (int c = 0; c < 8; ++c) {
        if (c & MC) continue;
        const int cl = c, ch = c | MC;
        float send = lo ? yr[ch] : yr[cl];
        float recv = __shfl_xor_sync(0xffffffffu, send, ML);
        if (lo) yr[ch] = recv; else yr[cl] = recv;
    }
}

// y[j] <- W[s][j][0]*y[j] + W[s][j][1]*y[j ^ (1<<s)]
// Phase 1 (stages 0..7), all butterflies IN-REGISTER via layout swaps:
//   layout 0: regs = j[0:2], lanes = j[3:7]          -> stages 0,1,2
//   swap A (3 bit-swaps): regs = j[3:5], lanes = j[0:2],j[6:7] -> stages 3,4,5
//   swap B (2 bit-swaps): regs = j[6],j[7],j[5], lanes = j[0:4] -> stages 6,7
// One swizzled smem store (scalar, conflict-free).
// Phase 2 (stages 8..11): gather j = b11*2048 + k*256 + low8, stages 8-10
// in-register on k, stage 11 via shfl mask 16. Direct global store.
__global__ __launch_bounds__(TPB, 1)
void butterfly_kernel(const float* __restrict__ x,
                      const float* __restrict__ W,
                      float* __restrict__ out)
{
    extern __shared__ float sm[];   // RROWS * LCOLS floats = 128 KB
    const int tid  = threadIdx.x;
    const int row0 = blockIdx.x * RROWS;
    const int l    = tid & 31;
    const int w    = tid >> 5;
    const int j0   = tid * 8;
    const bool lo1 = (l & 1) == 0;
    const bool lo2 = (l & 2) == 0;
    const bool lo4 = (l & 4) == 0;
    const bool lo8 = (l & 8) == 0;
    const bool lo16 = (l & 16) == 0;

    float y[RROWS][8];

    // ---- load 8 rows x 8 contiguous cols (layout 0) ----
    #pragma unroll
    for (int r = 0; r < RROWS; ++r) {
        const float4* p = reinterpret_cast<const float4*>(
            x + (size_t)(row0 + r) * LCOLS + j0);
        float4 a = __ldg(p);
        float4 b = __ldg(p + 1);
        y[r][0]=a.x; y[r][1]=a.y; y[r][2]=a.z; y[r][3]=a.w;
        y[r][4]=b.x; y[r][5]=b.y; y[r][6]=b.z; y[r][7]=b.w;
    }

    // element j of register c in layout A (after swap A):
    const int jc1 = (l & 7) + ((l >> 3) & 3) * 64 + w * 256;   // + 8*c
    // element j of register c in layout B (after swap B):
    const int jc2 = l + w * 256;   // + ((c&1)<<6) + (((c>>1)&1)<<7) + (((c>>2)&1)<<5)

    // ---- stages 0..2 : in-register on regs = j[0:2], float4 weights ----
    float4 wA, wB, wC, wD;
    {
        const float4* wp = reinterpret_cast<const float4*>(W + (size_t)j0 * 2);
        wA = __ldg(wp + 0); wB = __ldg(wp + 1);
        wC = __ldg(wp + 2); wD = __ldg(wp + 3);
    }
    #pragma unroll
    for (int s = 0; s < 3; ++s) {
        float4 nA, nB, nC, nD;
        if (s < 2) {
            const float4* np = reinterpret_cast<const float4*>(
                W + (size_t)(s + 1) * (LCOLS * 2) + j0 * 2);
            nA = __ldg(np + 0); nB = __ldg(np + 1);
            nC = __ldg(np + 2); nD = __ldg(np + 3);
        }
        float w0[8], w1[8];
        w0[0]=wA.x; w1[0]=wA.y; w0[1]=wA.z; w1[1]=wA.w;
        w0[2]=wB.x; w1[2]=wB.y; w0[3]=wB.z; w1[3]=wB.w;
        w0[4]=wC.x; w1[4]=wC.y; w0[5]=wC.z; w1[5]=wC.w;
        w0[6]=wD.x; w1[6]=wD.y; w0[7]=wD.z; w1[7]=wD.w;

        const int d = 1 << s;
        #pragma unroll
        for (int r = 0; r < RROWS; ++r) {
            float nt[8];
            #pragma unroll
            for (int c = 0; c < 8; ++c)
                nt[c] = fmaf(w0[c], y[r][c], w1[c] * y[r][c ^ d]);
            #pragma unroll
            for (int c = 0; c < 8; ++c) y[r][c] = nt[c];
        }
        if (s < 2) { wA = nA; wB = nB; wC = nC; wD = nD; }
    }

    // ---- prefetch stage-3 weights (layout A addresses), then swap A ----
    float w0c[8], w1c[8], w0n[8], w1n[8];
    #pragma unroll
    for (int c = 0; c < 8; ++c) {
        const float2 ww = __ldg(reinterpret_cast<const float2*>(
            W + (size_t)3 * (LCOLS * 2) + 2 * (jc1 + 8 * c)));
        w0c[c] = ww.x; w1c[c] = ww.y;
    }

    #pragma unroll
    for (int r = 0; r < RROWS; ++r) {
        bitswap<1, 1>(y[r], lo1);
        bitswap<2, 2>(y[r], lo2);
        bitswap<4, 4>(y[r], lo4);
    }

    // ---- stages 3..5 : in-register on regs = j[3:5] ----
    #pragma unroll
    for (int s = 3; s < 6; ++s) {
        // prefetch next stage's weights: stage 4,5 use layout A; stage 6 layout B
        if (s < 5) {
            #pragma unroll
            for (int c = 0; c < 8; ++c) {
                const float2 ww = __ldg(reinterpret_cast<const float2*>(
                    W + (size_t)(s + 1) * (LCOLS * 2) + 2 * (jc1 + 8 * c)));
                w0n[c] = ww.x; w1n[c] = ww.y;
            }
        } else {
            #pragma unroll
            for (int c = 0; c < 8; ++c) {
                const int jb = jc2 + ((c & 1) << 6) + (((c >> 1) & 1) << 7)
                             + (((c >> 2) & 1) << 5);
                const float2 ww = __ldg(reinterpret_cast<const float2*>(
                    W + (size_t)6 * (LCOLS * 2) + 2 * jb));
                w0n[c] = ww.x; w1n[c] = ww.y;
            }
        }
        const int d = 1 << (s - 3);
        #pragma unroll
        for (int r = 0; r < RROWS; ++r) {
            float nt[8];
            #pragma unroll
            for (int c = 0; c < 8; ++c)
                nt[c] = fmaf(w0c[c], y[r][c], w1c[c] * y[r][c ^ d]);
            #pragma unroll
            for (int c = 0; c < 8; ++c) y[r][c] = nt[c];
        }
        #pragma unroll
        for (int c = 0; c < 8; ++c) { w0c[c] = w0n[c]; w1c[c] = w1n[c]; }
    }

    // ---- swap B : regs become j[6],j[7] (c2 keeps j[5]) ----
    #pragma unroll
    for (int r = 0; r < RROWS; ++r) {
        bitswap<1, 8>(y[r], lo8);
        bitswap<2, 16>(y[r], lo16);
    }

    // ---- stages 6..7 : in-register on c0=j[6], c1=j[7] ----
    #pragma unroll
    for (int s = 6; s < 8; ++s) {
        if (s == 6) {   // prefetch stage-7 weights (layout B)
            #pragma unroll
            for (int c = 0; c < 8; ++c) {
                const int jb = jc2 + ((c & 1) << 6) + (((c >> 1) & 1) << 7)
                             + (((c >> 2) & 1) << 5);
                const float2 ww = __ldg(reinterpret_cast<const float2*>(
                    W + (size_t)7 * (LCOLS * 2) + 2 * jb));
                w0n[c] = ww.x; w1n[c] = ww.y;
            }
        }
        const int d = 1 << (s - 6);   // stage 6 -> c^1 (j6), stage 7 -> c^2 (j7)
        #pragma unroll
        for (int r = 0; r < RROWS; ++r) {
            float nt[8];
            #pragma unroll
            for (int c = 0; c < 8; ++c)
                nt[c] = fmaf(w0c[c], y[r][c], w1c[c] * y[r][c ^ d]);
            #pragma unroll
            for (int c = 0; c < 8; ++c) y[r][c] = nt[c];
        }
        if (s == 6) {
            #pragma unroll
            for (int c = 0; c < 8; ++c) { w0c[c] = w0n[c]; w1c[c] = w1n[c]; }
        }
    }

    // ---- swizzled smem store: element j lands at sm[swz(j)] ----
    {
        int sj[8];
        #pragma unroll
        for (int c = 0; c < 8; ++c) {
            const int jb = jc2 + ((c & 1) << 6) + (((c >> 1) & 1) << 7)
                         + (((c >> 2) & 1) << 5);
            sj[c] = swz(jb);
        }
        #pragma unroll
        for (int r = 0; r < RROWS; ++r)
            #pragma unroll
            for (int c = 0; c < 8; ++c)
                sm[r * LCOLS + sj[c]] = y[r][c];
    }
    __syncthreads();

    // ---- phase 2: stages 8..11 ----
    const int b11   = l >> 4;                // stage-11 partner = lane ^ 16
    const int low8  = (w << 4) | (l & 15);   // bits 0..7 of j
    const int jbase = b11 * 2048 + low8;     // j(k) = jbase + k*256
    const int sjbase = swz(jbase);

    float w0p[4][8], w1p[4][8];
    #pragma unroll
    for (int s4 = 0; s4 < 4; ++s4) {
        #pragma unroll
        for (int k = 0; k < 8; ++k) {
            const float2 ww = __ldg(reinterpret_cast<const float2*>(
                W + (size_t)(8 + s4) * (LCOLS * 2) + 2 * (jbase + k * 256)));
            w0p[s4][k] = ww.x;
            w1p[s4][k] = ww.y;
        }
    }

    float vnext[8];
    #pragma unroll
    for (int k = 0; k < 8; ++k)
        vnext[k] = sm[sjbase + k * 256];

    #pragma unroll
    for (int r = 0; r < RROWS; ++r) {
        float v[8];
        #pragma unroll
        for (int k = 0; k < 8; ++k) v[k] = vnext[k];

        if (r < RROWS - 1) {
            #pragma unroll
            for (int k = 0; k < 8; ++k)
                vnext[k] = sm[(r + 1) * LCOLS + sjbase + k * 256];
        }

        #pragma unroll
        for (int sb = 0; sb < 3; ++sb) {
            const int d = 1 << sb;
            float nv[8];
            #pragma unroll
            for (int k = 0; k < 8; ++k)
                nv[k] = fmaf(w0p[sb][k], v[k], w1p[sb][k] * v[k ^ d]);
            #pragma unroll
            for (int k = 0; k < 8; ++k) v[k] = nv[k];
        }

        #pragma unroll
        for (int k = 0; k < 8; ++k) {
            float p = __shfl_xor_sync(0xffffffffu, v[k], 16);
            v[k] = fmaf(w0p[3][k], v[k], w1p[3][k] * p);
        }

        float* op = out + (size_t)(row0 + r) * LCOLS + jbase;
        #pragma unroll
        for (int k = 0; k < 8; ++k)
            op[k * 256] = v[k];
    }
}

extern "C" void kernel_launch(void* const* d_in, const int* in_sizes, int n_in,
                              void* d_out, int out_size) {
    const float* x;
    const float* W;
    if (in_sizes[0] == NSTAGES * LCOLS * 2) {   // W has 98304 elements
        W = (const float*)d_in[0];
        x = (const float*)d_in[1];
    } else {
        x = (const float*)d_in[0];
        W = (const float*)d_in[1];
    }
    float* out = (float*)d_out;

    const int smem_bytes = RROWS * LCOLS * sizeof(float);  // 128 KB
    cudaFuncSetAttribute(butterfly_kernel,
                         cudaFuncAttributeMaxDynamicSharedMemorySize, smem_bytes);
    butterfly_kernel<<<NBATCH / RROWS, TPB, smem_bytes>>>(x, W, out);
}

// round 8
// speedup vs baseline: 1.3415x; 1.0089x over previous
#include <cuda_runtime.h>

#define LCOLS 4096
#define NSTAGES 12
#define RROWS 8
#define NPAIR 4
#define TPB 512
#define NBATCH 8192

typedef unsigned long long ull;

// Swizzle: XOR bit4 with j's bit11, bit2 with j's bit5.
__device__ __forceinline__ int swz(int j) {
    return j ^ (((j >> 11) & 1) << 4) ^ (((j >> 5) & 1) << 2);
}

// ---- packed f32x2 helpers (FFMA2/FMUL2 are PTX-only on sm_103a) ----
__device__ __forceinline__ ull pack2(float a, float b) {
    ull r; asm("mov.b64 %0, {%1, %2};" : "=l"(r) : "f"(a), "f"(b)); return r;
}
__device__ __forceinline__ void unpack2(ull v, float& a, float& b) {
    asm("mov.b64 {%0, %1}, %2;" : "=f"(a), "=f"(b) : "l"(v));
}
__device__ __forceinline__ ull dup2(float a) { return pack2(a, a); }
__device__ __forceinline__ ull mul2(ull a, ull b) {
    ull d; asm("mul.rn.f32x2 %0, %1, %2;" : "=l"(d) : "l"(a), "l"(b)); return d;
}
__device__ __forceinline__ ull fma2(ull a, ull b, ull c) {
    ull d; asm("fma.rn.f32x2 %0, %1, %2, %3;" : "=l"(d) : "l"(a), "l"(b), "l"(c)); return d;
}

// packed in-register butterfly on reg-bit D, weights scalar (shared by both rows)
template <int D>
__device__ __forceinline__ void bfly2(ull Y[NPAIR][8],
                                      const float* w0, const float* w1) {
    #pragma unroll
    for (int c = 0; c < 8; ++c) {
        if (c & D) continue;
        const int ch = c | D;
        const ull W0l = dup2(w0[c]),  W1l = dup2(w1[c]);
        const ull W0h = dup2(w0[ch]), W1h = dup2(w1[ch]);
        #pragma unroll
        for (int p = 0; p < NPAIR; ++p) {
            const ull a = Y[p][c], b = Y[p][ch];
            Y[p][c]  = fma2(W0l, a, mul2(W1l, b));
            Y[p][ch] = fma2(W0h, b, mul2(W1h, a));
        }
    }
}

// Swap roles of register bit MC and lane bit ML (both packed rows together).
template <int MC, int ML>
__device__ __forceinline__ void bitswap2(ull* yr, bool lo) {
    #pragma unroll
    for (int c = 0; c < 8; ++c) {
        if (c & MC) continue;
        const int cl = c, ch = c | MC;
        ull send = lo ? yr[ch] : yr[cl];
        ull recv = __shfl_xor_sync(0xffffffffu, send, ML);
        if (lo) yr[ch] = recv; else yr[cl] = recv;
    }
}

// y[j] <- W[s][j][0]*y[j] + W[s][j][1]*y[j ^ (1<<s)]
// Rows packed in pairs into f32x2 (weights identical across rows).
// Phase 1 (stages 0..7), all butterflies in-register via layout swaps:
//   layout 0: regs = j[0:2]                       -> stages 0,1,2
//   swap A:   regs = j[3:5]                       -> stages 3,4,5
//   swap B:   regs = j[6],j[7],j[5]               -> stages 6,7
// One swizzled smem store. Phase 2 (stages 8..11): packed stage-major,
// stages 8-10 in-register on k, stage 11 via shfl mask 16. Direct global store.
__global__ __launch_bounds__(TPB, 1)
void butterfly_kernel(const float* __restrict__ x,
                      const float* __restrict__ W,
                      float* __restrict__ out)
{
    extern __shared__ float sm[];   // RROWS * LCOLS floats = 128 KB
    const int tid  = threadIdx.x;
    const int row0 = blockIdx.x * RROWS;
    const int l    = tid & 31;
    const int w    = tid >> 5;
    const int j0   = tid * 8;
    const bool lo1 = (l & 1) == 0;
    const bool lo2 = (l & 2) == 0;
    const bool lo4 = (l & 4) == 0;
    const bool lo8 = (l & 8) == 0;
    const bool lo16 = (l & 16) == 0;

    ull Y[NPAIR][8];

    // ---- load 8 rows x 8 contiguous cols, pack row-pairs ----
    #pragma unroll
    for (int p = 0; p < NPAIR; ++p) {
        const float4* p0 = reinterpret_cast<const float4*>(
            x + (size_t)(row0 + 2 * p) * LCOLS + j0);
        const float4* p1 = reinterpret_cast<const float4*>(
            x + (size_t)(row0 + 2 * p + 1) * LCOLS + j0);
        float4 a0 = __ldg(p0), b0 = __ldg(p0 + 1);
        float4 a1 = __ldg(p1), b1 = __ldg(p1 + 1);
        Y[p][0] = pack2(a0.x, a1.x); Y[p][1] = pack2(a0.y, a1.y);
        Y[p][2] = pack2(a0.z, a1.z); Y[p][3] = pack2(a0.w, a1.w);
        Y[p][4] = pack2(b0.x, b1.x); Y[p][5] = pack2(b0.y, b1.y);
        Y[p][6] = pack2(b0.z, b1.z); Y[p][7] = pack2(b0.w, b1.w);
    }

    // element j of register c in layout A (after swap A):
    const int jc1 = (l & 7) + ((l >> 3) & 3) * 64 + w * 256;   // + 8*c
    // element j of register c in layout B (after swap B):
    const int jc2 = l + w * 256;   // + ((c&1)<<6) + (((c>>1)&1)<<7) + (((c>>2)&1)<<5)

    // ---- stages 0..2 : regs = j[0:2], float4 weights, double-buffered ----
    float4 wA, wB, wC, wD;
    {
        const float4* wp = reinterpret_cast<const float4*>(W + (size_t)j0 * 2);
        wA = __ldg(wp + 0); wB = __ldg(wp + 1);
        wC = __ldg(wp + 2); wD = __ldg(wp + 3);
    }
    #pragma unroll
    for (int s = 0; s < 3; ++s) {
        float4 nA, nB, nC, nD;
        if (s < 2) {
            const float4* np = reinterpret_cast<const float4*>(
                W + (size_t)(s + 1) * (LCOLS * 2) + j0 * 2);
            nA = __ldg(np + 0); nB = __ldg(np + 1);
            nC = __ldg(np + 2); nD = __ldg(np + 3);
        }
        float w0[8], w1[8];
        w0[0]=wA.x; w1[0]=wA.y; w0[1]=wA.z; w1[1]=wA.w;
        w0[2]=wB.x; w1[2]=wB.y; w0[3]=wB.z; w1[3]=wB.w;
        w0[4]=wC.x; w1[4]=wC.y; w0[5]=wC.z; w1[5]=wC.w;
        w0[6]=wD.x; w1[6]=wD.y; w0[7]=wD.z; w1[7]=wD.w;

        if (s == 0) bfly2<1>(Y, w0, w1);
        else if (s == 1) bfly2<2>(Y, w0, w1);
        else bfly2<4>(Y, w0, w1);

        if (s < 2) { wA = nA; wB = nB; wC = nC; wD = nD; }
    }

    // ---- prefetch stage-3 weights (layout A), then swap A ----
    float w0c[8], w1c[8], w0n[8], w1n[8];
    #pragma unroll
    for (int c = 0; c < 8; ++c) {
        const float2 ww = __ldg(reinterpret_cast<const float2*>(
            W + (size_t)3 * (LCOLS * 2) + 2 * (jc1 + 8 * c)));
        w0c[c] = ww.x; w1c[c] = ww.y;
    }

    #pragma unroll
    for (int p = 0; p < NPAIR; ++p) {
        bitswap2<1, 1>(Y[p], lo1);
        bitswap2<2, 2>(Y[p], lo2);
        bitswap2<4, 4>(Y[p], lo4);
    }

    // ---- stages 3..5 : regs = j[3:5] ----
    #pragma unroll
    for (int s = 3; s < 6; ++s) {
        if (s < 5) {
            #pragma unroll
            for (int c = 0; c < 8; ++c) {
                const float2 ww = __ldg(reinterpret_cast<const float2*>(
                    W + (size_t)(s + 1) * (LCOLS * 2) + 2 * (jc1 + 8 * c)));
                w0n[c] = ww.x; w1n[c] = ww.y;
            }
        } else {
            #pragma unroll
            for (int c = 0; c < 8; ++c) {
                const int jb = jc2 + ((c & 1) << 6) + (((c >> 1) & 1) << 7)
                             + (((c >> 2) & 1) << 5);
                const float2 ww = __ldg(reinterpret_cast<const float2*>(
                    W + (size_t)6 * (LCOLS * 2) + 2 * jb));
                w0n[c] = ww.x; w1n[c] = ww.y;
            }
        }
        if (s == 3) bfly2<1>(Y, w0c, w1c);
        else if (s == 4) bfly2<2>(Y, w0c, w1c);
        else bfly2<4>(Y, w0c, w1c);
        #pragma unroll
        for (int c = 0; c < 8; ++c) { w0c[c] = w0n[c]; w1c[c] = w1n[c]; }
    }

    // ---- swap B : regs become j[6],j[7] (c2 keeps j[5]) ----
    #pragma unroll
    for (int p = 0; p < NPAIR; ++p) {
        bitswap2<1, 8>(Y[p], lo8);
        bitswap2<2, 16>(Y[p], lo16);
    }

    // ---- stages 6..7 : c0=j[6], c1=j[7] ----
    {
        #pragma unroll
        for (int c = 0; c < 8; ++c) {
            const int jb = jc2 + ((c & 1) << 6) + (((c >> 1) & 1) << 7)
                         + (((c >> 2) & 1) << 5);
            const float2 ww = __ldg(reinterpret_cast<const float2*>(
                W + (size_t)7 * (LCOLS * 2) + 2 * jb));
            w0n[c] = ww.x; w1n[c] = ww.y;
        }
        bfly2<1>(Y, w0c, w1c);             // stage 6
        bfly2<2>(Y, w0n, w1n);             // stage 7
    }

    // ---- swizzled smem store: element j lands at sm[swz(j)] ----
    {
        int sj[8];
        #pragma unroll
        for (int c = 0; c < 8; ++c) {
            const int jb = jc2 + ((c & 1) << 6) + (((c >> 1) & 1) << 7)
                         + (((c >> 2) & 1) << 5);
            sj[c] = swz(jb);
        }
        #pragma unroll
        for (int p = 0; p < NPAIR; ++p)
            #pragma unroll
            for (int c = 0; c < 8; ++c) {
                float a, b;
                unpack2(Y[p][c], a, b);
                sm[(2 * p) * LCOLS + sj[c]] = a;
                sm[(2 * p + 1) * LCOLS + sj[c]] = b;
            }
    }
    __syncthreads();

    // ---- phase 2: stages 8..11, packed stage-major ----
    const int b11   = l >> 4;                // stage-11 partner = lane ^ 16
    const int low8  = (w << 4) | (l & 15);   // bits 0..7 of j
    const int jbase = b11 * 2048 + low8;     // j(k) = jbase + k*256
    const int sjbase = swz(jbase);

    // stage-8 weights first (overlap with gathers)
    float w0s[8], w1s[8];
    #pragma unroll
    for (int k = 0; k < 8; ++k) {
        const float2 ww = __ldg(reinterpret_cast<const float2*>(
            W + (size_t)8 * (LCOLS * 2) + 2 * (jbase + k * 256)));
        w0s[k] = ww.x; w1s[k] = ww.y;
    }

    // gather all 4 pairs (64 independent LDS = high MLP)
    ull V[NPAIR][8];
    #pragma unroll
    for (int p = 0; p < NPAIR; ++p)
        #pragma unroll
        for (int k = 0; k < 8; ++k) {
            const float a = sm[(2 * p) * LCOLS + sjbase + k * 256];
            const float b = sm[(2 * p + 1) * LCOLS + sjbase + k * 256];
            V[p][k] = pack2(a, b);
        }

    // stages 8..10 in-register on k bits, per-stage weight double-buffer
    #pragma unroll
    for (int sb = 0; sb < 3; ++sb) {
        #pragma unroll
        for (int k = 0; k < 8; ++k) {   // prefetch next stage (9,10,11)
            const float2 ww = __ldg(reinterpret_cast<const float2*>(
                W + (size_t)(9 + sb) * (LCOLS * 2) + 2 * (jbase + k * 256)));
            w0n[k] = ww.x; w1n[k] = ww.y;
        }
        if (sb == 0) bfly2<1>(V, w0s, w1s);
        else if (sb == 1) bfly2<2>(V, w0s, w1s);
        else bfly2<4>(V, w0s, w1s);
        #pragma unroll
        for (int k = 0; k < 8; ++k) { w0s[k] = w0n[k]; w1s[k] = w1n[k]; }
    }

    // stage 11 : partner is lane^16
    #pragma unroll
    for (int k = 0; k < 8; ++k) {
        const ull W0 = dup2(w0s[k]), W1 = dup2(w1s[k]);
        #pragma unroll
        for (int p = 0; p < NPAIR; ++p) {
            ull pr = __shfl_xor_sync(0xffffffffu, V[p][k], 16);
            V[p][k] = fma2(W0, V[p][k], mul2(W1, pr));
        }
    }

    // direct global store: per k, lanes 0-15 / 16-31 each cover 64B runs
    #pragma unroll
    for (int p = 0; p < NPAIR; ++p) {
        float* op0 = out + (size_t)(row0 + 2 * p) * LCOLS + jbase;
        float* op1 = out + (size_t)(row0 + 2 * p + 1) * LCOLS + jbase;
        #pragma unroll
        for (int k = 0; k < 8; ++k) {
            float a, b;
            unpack2(V[p][k], a, b);
            op0[k * 256] = a;
            op1[k * 256] = b;
        }
    }
}

extern "C" void kernel_launch(void* const* d_in, const int* in_sizes, int n_in,
                              void* d_out, int out_size) {
    const float* x;
    const float* W;
    if (in_sizes[0] == NSTAGES * LCOLS * 2) {   // W has 98304 elements
        W = (const float*)d_in[0];
        x = (const float*)d_in[1];
    } else {
        x = (const float*)d_in[0];
        W = (const float*)d_in[1];
    }
    float* out = (float*)d_out;

    const int smem_bytes = RROWS * LCOLS * sizeof(float);  // 128 KB
    cudaFuncSetAttribute(butterfly_kernel,
                         cudaFuncAttributeMaxDynamicSharedMemorySize, smem_bytes);
    butterfly_kernel<<<NBATCH / RROWS, TPB, smem_bytes>>>(x, W, out);
}

// round 9
// speedup vs baseline: 1.3424x; 1.0007x over previous
#include <cuda_runtime.h>

#define LCOLS 4096
#define NSTAGES 12
#define RROWS 8
#define NPAIR 4
#define TPB 1024
#define NBATCH 8192

typedef unsigned long long ull;

// ---- packed f32x2 helpers (FFMA2/FMUL2 are PTX-only on sm_103a) ----
__device__ __forceinline__ ull pack2(float a, float b) {
    ull r; asm("mov.b64 %0, {%1, %2};" : "=l"(r) : "f"(a), "f"(b)); return r;
}
__device__ __forceinline__ void unpack2(ull v, float& a, float& b) {
    asm("mov.b64 {%0, %1}, %2;" : "=f"(a), "=f"(b) : "l"(v));
}
__device__ __forceinline__ ull dup2(float a) { return pack2(a, a); }
__device__ __forceinline__ ull mul2(ull a, ull b) {
    ull d; asm("mul.rn.f32x2 %0, %1, %2;" : "=l"(d) : "l"(a), "l"(b)); return d;
}
__device__ __forceinline__ ull fma2(ull a, ull b, ull c) {
    ull d; asm("fma.rn.f32x2 %0, %1, %2, %3;" : "=l"(d) : "l"(a), "l"(b), "l"(c)); return d;
}

// packed butterfly on reg-bit D over 4 regs; weights shared by both packed rows
template <int D>
__device__ __forceinline__ void bfly2(ull Y[NPAIR][4],
                                      const float* w0, const float* w1) {
    #pragma unroll
    for (int c = 0; c < 4; ++c) {
        if (c & D) continue;
        const int ch = c | D;
        const ull W0l = dup2(w0[c]),  W1l = dup2(w1[c]);
        const ull W0h = dup2(w0[ch]), W1h = dup2(w1[ch]);
        #pragma unroll
        for (int p = 0; p < NPAIR; ++p) {
            const ull a = Y[p][c], b = Y[p][ch];
            Y[p][c]  = fma2(W0l, a, mul2(W1l, b));
            Y[p][ch] = fma2(W0h, b, mul2(W1h, a));
        }
    }
}

// swap roles of register bit MC and lane bit ML (half-exchange, 2 shfl / 4 regs)
template <int MC, int ML>
__device__ __forceinline__ void bitswap2(ull* yr, bool lo) {
    #pragma unroll
    for (int c = 0; c < 4; ++c) {
        if (c & MC) continue;
        const int ch = c | MC;
        ull send = lo ? yr[ch] : yr[c];
        ull recv = __shfl_xor_sync(0xffffffffu, send, ML);
        if (lo) yr[ch] = recv; else yr[c] = recv;
    }
}

// shared-memory physical swizzle: bank bit 4 ^= address bit 11
__device__ __forceinline__ int phys(int a) {
    return a ^ (((a >> 11) & 1) << 4);
}

// y[j] <- W[s][j][0]*y[j] + W[s][j][1]*y[j ^ (1<<s)]
// TPB=1024: thread owns 4 cols (2 reg bits), 32 warps/SM for latency hiding.
// Phase 1 (stages 0..6): regs j[0:1] -> swapA j[2:3] -> swapB j[4:5] -> swapC j[6].
// Round 1 (stages 7..8): smem gather regs=j[7:8], in-place writeback.
// Round 2 (stages 9..11): smem gather regs=j[9:10], stage 11 shfl mask 16,
// direct global store (64B runs).
__global__ __launch_bounds__(TPB, 1)
void butterfly_kernel(const float* __restrict__ x,
                      const float* __restrict__ W,
                      float* __restrict__ out)
{
    extern __shared__ float sm[];   // RROWS * LCOLS floats = 128 KB
    const int tid  = threadIdx.x;
    const int row0 = blockIdx.x * RROWS;
    const int l    = tid & 31;
    const int w    = tid >> 5;
    const int j0   = tid * 4;
    const bool lo1  = (l & 1) == 0;
    const bool lo2  = (l & 2) == 0;
    const bool lo4  = (l & 4) == 0;
    const bool lo8  = (l & 8) == 0;
    const bool lo16 = (l & 16) == 0;

    ull Y[NPAIR][4];

    // ---- load 8 rows x 4 contiguous cols, pack row-pairs ----
    #pragma unroll
    for (int p = 0; p < NPAIR; ++p) {
        float4 a0 = __ldg(reinterpret_cast<const float4*>(
            x + (size_t)(row0 + 2 * p) * LCOLS + j0));
        float4 a1 = __ldg(reinterpret_cast<const float4*>(
            x + (size_t)(row0 + 2 * p + 1) * LCOLS + j0));
        Y[p][0] = pack2(a0.x, a1.x); Y[p][1] = pack2(a0.y, a1.y);
        Y[p][2] = pack2(a0.z, a1.z); Y[p][3] = pack2(a0.w, a1.w);
    }

    float w0[4], w1[4];

    // ---- stages 0,1 : regs = j[0:1], weights 2x float4 contiguous ----
    #pragma unroll
    for (int s = 0; s < 2; ++s) {
        const float4* wp = reinterpret_cast<const float4*>(
            W + (size_t)s * (LCOLS * 2) + j0 * 2);
        float4 wA = __ldg(wp), wB = __ldg(wp + 1);
        w0[0]=wA.x; w1[0]=wA.y; w0[1]=wA.z; w1[1]=wA.w;
        w0[2]=wB.x; w1[2]=wB.y; w0[3]=wB.z; w1[3]=wB.w;
        if (s == 0) bfly2<1>(Y, w0, w1); else bfly2<2>(Y, w0, w1);
    }

    // ---- swap A : regs = j[2:3] ; stages 2,3 ----
    #pragma unroll
    for (int p = 0; p < NPAIR; ++p) {
        bitswap2<1, 1>(Y[p], lo1);
        bitswap2<2, 2>(Y[p], lo2);
    }
    const int jA = (l & 3) + ((l >> 2) & 7) * 16 + w * 128;   // j = jA + 4c
    #pragma unroll
    for (int s = 2; s < 4; ++s) {
        #pragma unroll
        for (int c = 0; c < 4; ++c) {
            const float2 ww = __ldg(reinterpret_cast<const float2*>(
                W + (size_t)s * (LCOLS * 2) + 2 * (jA + 4 * c)));
            w0[c] = ww.x; w1[c] = ww.y;
        }
        if (s == 2) bfly2<1>(Y, w0, w1); else bfly2<2>(Y, w0, w1);
    }

    // ---- swap B : regs = j[4:5] ; stages 4,5 ----
    #pragma unroll
    for (int p = 0; p < NPAIR; ++p) {
        bitswap2<1, 4>(Y[p], lo4);
        bitswap2<2, 8>(Y[p], lo8);
    }
    const int jB = (l & 15) + ((l >> 4) & 1) * 64 + w * 128;  // j = jB + 16c
    #pragma unroll
    for (int s = 4; s < 6; ++s) {
        #pragma unroll
        for (int c = 0; c < 4; ++c) {
            const float2 ww = __ldg(reinterpret_cast<const float2*>(
                W + (size_t)s * (LCOLS * 2) + 2 * (jB + 16 * c)));
            w0[c] = ww.x; w1[c] = ww.y;
        }
        if (s == 4) bfly2<1>(Y, w0, w1); else bfly2<2>(Y, w0, w1);
    }

    // ---- swap C : reg bit0 = j[6] (bit1 stays j[5]) ; stage 6 ----
    #pragma unroll
    for (int p = 0; p < NPAIR; ++p)
        bitswap2<1, 16>(Y[p], lo16);
    const int jC = (l & 15) + ((l >> 4) & 1) * 16 + w * 128;
    // j(c) = jC + (c&1)*64 + ((c>>1)&1)*32
    {
        #pragma unroll
        for (int c = 0; c < 4; ++c) {
            const int jb = jC + ((c & 1) << 6) + (((c >> 1) & 1) << 5);
            const float2 ww = __ldg(reinterpret_cast<const float2*>(
                W + (size_t)6 * (LCOLS * 2) + 2 * jb));
            w0[c] = ww.x; w1[c] = ww.y;
        }
        bfly2<1>(Y, w0, w1);
    }

    // ---- store to smem at phys(j) ----
    {
        int sj[4];
        #pragma unroll
        for (int c = 0; c < 4; ++c)
            sj[c] = phys(jC + ((c & 1) << 6) + (((c >> 1) & 1) << 5));
        #pragma unroll
        for (int p = 0; p < NPAIR; ++p)
            #pragma unroll
            for (int c = 0; c < 4; ++c) {
                float a, b;
                unpack2(Y[p][c], a, b);
                sm[(2 * p) * LCOLS + sj[c]] = a;
                sm[(2 * p + 1) * LCOLS + sj[c]] = b;
            }
    }
    __syncthreads();

    // ---- round 1 : stages 7,8 (regs = j[7:8]) ----
    // lanes = j[0:4]; warp bits = (j5, j6, j9, j10, j11)
    const int base1 = l + (w & 1) * 32 + ((w >> 1) & 1) * 64
                    + ((w >> 2) & 1) * 512 + ((w >> 3) & 1) * 1024
                    + ((w >> 4) & 1) * 2048;            // j = base1 + 128c
    const int pb1 = phys(base1);                        // bit11 const, no carry
    {
        ull V[NPAIR][4];
        #pragma unroll
        for (int p = 0; p < NPAIR; ++p)
            #pragma unroll
            for (int c = 0; c < 4; ++c) {
                const float a = sm[(2 * p) * LCOLS + pb1 + 128 * c];
                const float b = sm[(2 * p + 1) * LCOLS + pb1 + 128 * c];
                V[p][c] = pack2(a, b);
            }

        #pragma unroll
        for (int s = 7; s < 9; ++s) {
            #pragma unroll
            for (int c = 0; c < 4; ++c) {
                const float2 ww = __ldg(reinterpret_cast<const float2*>(
                    W + (size_t)s * (LCOLS * 2) + 2 * (base1 + 128 * c)));
                w0[c] = ww.x; w1[c] = ww.y;
            }
            if (s == 7) bfly2<1>(V, w0, w1); else bfly2<2>(V, w0, w1);
        }

        // in-place writeback (each element owned by exactly this thread)
        #pragma unroll
        for (int p = 0; p < NPAIR; ++p)
            #pragma unroll
            for (int c = 0; c < 4; ++c) {
                float a, b;
                unpack2(V[p][c], a, b);
                sm[(2 * p) * LCOLS + pb1 + 128 * c] = a;
                sm[(2 * p + 1) * LCOLS + pb1 + 128 * c] = b;
            }
    }
    __syncthreads();

    // ---- round 2 : stages 9,10 (regs = j[9:10]), stage 11 (lane bit 4) ----
    // lanes = (j0..j3, j11); warp bits = j[4:8]
    const int base2 = (l & 15) + w * 16 + ((l >> 4) & 1) * 2048;  // j = base2 + 512c
    const int pb2 = base2 ^ (((l >> 4) & 1) << 4);                // phys, no carry
    {
        ull V[NPAIR][4];
        #pragma unroll
        for (int p = 0; p < NPAIR; ++p)
            #pragma unroll
            for (int c = 0; c < 4; ++c) {
                const float a = sm[(2 * p) * LCOLS + pb2 + 512 * c];
                const float b = sm[(2 * p + 1) * LCOLS + pb2 + 512 * c];
                V[p][c] = pack2(a, b);
            }

        #pragma unroll
        for (int s = 9; s < 11; ++s) {
            #pragma unroll
            for (int c = 0; c < 4; ++c) {
                const float2 ww = __ldg(reinterpret_cast<const float2*>(
                    W + (size_t)s * (LCOLS * 2) + 2 * (base2 + 512 * c)));
                w0[c] = ww.x; w1[c] = ww.y;
            }
            if (s == 9) bfly2<1>(V, w0, w1); else bfly2<2>(V, w0, w1);
        }

        // stage 11 : partner is lane^16 (j11)
        #pragma unroll
        for (int c = 0; c < 4; ++c) {
            const float2 ww = __ldg(reinterpret_cast<const float2*>(
                W + (size_t)11 * (LCOLS * 2) + 2 * (base2 + 512 * c)));
            w0[c] = ww.x; w1[c] = ww.y;
        }
        #pragma unroll
        for (int c = 0; c < 4; ++c) {
            const ull W0 = dup2(w0[c]), W1 = dup2(w1[c]);
            #pragma unroll
            for (int p = 0; p < NPAIR; ++p) {
                ull pr = __shfl_xor_sync(0xffffffffu, V[p][c], 16);
                V[p][c] = fma2(W0, V[p][c], mul2(W1, pr));
            }
        }

        // direct global store: per c, lanes 0-15 / 16-31 each cover 64B runs
        #pragma unroll
        for (int p = 0; p < NPAIR; ++p) {
            float* op0 = out + (size_t)(row0 + 2 * p) * LCOLS + base2;
            float* op1 = out + (size_t)(row0 + 2 * p + 1) * LCOLS + base2;
            #pragma unroll
            for (int c = 0; c < 4; ++c) {
                float a, b;
                unpack2(V[p][c], a, b);
                op0[512 * c] = a;
                op1[512 * c] = b;
            }
        }
    }
}

extern "C" void kernel_launch(void* const* d_in, const int* in_sizes, int n_in,
                              void* d_out, int out_size) {
    const float* x;
    const float* W;
    if (in_sizes[0] == NSTAGES * LCOLS * 2) {   // W has 98304 elements
        W = (const float*)d_in[0];
        x = (const float*)d_in[1];
    } else {
        x = (const float*)d_in[0];
        W = (const float*)d_in[1];
    }
    float* out = (float*)d_out;

    const int smem_bytes = RROWS * LCOLS * sizeof(float);  // 128 KB
    cudaFuncSetAttribute(butterfly_kernel,
                         cudaFuncAttributeMaxDynamicSharedMemorySize, smem_bytes);
    butterfly_kernel<<<NBATCH / RROWS, TPB, smem_bytes>>>(x, W, out);
}